// round 14
// baseline (speedup 1.0000x reference)
#include <cuda_runtime.h>
#include <cuda_bf16.h>
#include <mma.h>
#include <cstdint>
#include <cstddef>

using namespace nvcuda;
typedef __nv_bfloat16 bf16;

#define BATCH 4
#define CQd   256
#define NQd   2048
#define NKVd  2048
#define NH    8
#define DKd   64
#define ODd   512   // NH*DKd
#define KSPLIT 8

// ---------------- scratch (static device globals; no runtime alloc) -------
__device__ __align__(16) bf16 g_xq [BATCH*CQd*NQd];
__device__ __align__(16) bf16 g_xkv[BATCH*CQd*NKVd];
__device__ __align__(16) bf16 g_Wq [ODd*CQd];
__device__ __align__(16) bf16 g_Wk [ODd*CQd];
__device__ __align__(16) bf16 g_Wv [ODd*CQd];
__device__ __align__(16) bf16 g_Wo [CQd*ODd];
__device__ __align__(16) bf16 g_Q  [BATCH*ODd*NQd];
__device__ __align__(16) bf16 g_K  [BATCH*ODd*NKVd];
__device__ __align__(16) bf16 g_V  [BATCH*ODd*NKVd];
__device__ __align__(16) float g_Mf [BATCH*NH*DKd*DKd];   // atomically accumulated K^T V
__device__ __align__(16) bf16 g_Wp [BATCH*CQd*ODd];       // fused Wo @ blockdiag(M^T)

// ---------------- fused fp32 -> bf16 conversion + g_Mf zeroing -------------
__global__ void convert_all_kernel(const float* __restrict__ xq,
                                   const float* __restrict__ xkv,
                                   const float* __restrict__ Wq,
                                   const float* __restrict__ Wk,
                                   const float* __restrict__ Wv,
                                   const float* __restrict__ Wo) {
    int i = blockIdx.x * blockDim.x + threadIdx.x;  // float4 index, total 1179648
    // fold the g_Mf zeroing into spare work here (g_Mf = 131072 floats = 32768 float4)
    if (i < 32768) ((float4*)g_Mf)[i] = make_float4(0.f, 0.f, 0.f, 0.f);

    const float* src; bf16* dst; int off;
    if (i < 524288)            { src = xq;  dst = g_xq;  off = i; }
    else if (i < 1048576)      { src = xkv; dst = g_xkv; off = i - 524288; }
    else {
        int j = i - 1048576;
        int w = j >> 15;  off = j & 32767;
        src = (w == 0) ? Wq : (w == 1) ? Wk : (w == 2) ? Wv : Wo;
        dst = (w == 0) ? g_Wq : (w == 1) ? g_Wk : (w == 2) ? g_Wv : g_Wo;
    }
    float4 v = ((const float4*)src)[off];
    __nv_bfloat162 two[2] = { __floats2bfloat162_rn(v.x, v.y),
                              __floats2bfloat162_rn(v.z, v.w) };
    *(uint2*)&dst[(size_t)off * 4] = *(uint2*)two;
}

// ---------------- cp.async helpers -----------------------------------------
__device__ __forceinline__ void cpa16(void* dst, const void* src) {
    unsigned int d = (unsigned int)__cvta_generic_to_shared(dst);
    asm volatile("cp.async.cg.shared.global [%0], [%1], 16;\n" :: "r"(d), "l"(src));
}
__device__ __forceinline__ void cpa_commit() {
    asm volatile("cp.async.commit_group;\n" ::);
}

// ---------------- pipelined TOxTNx32 bf16 GEMM core ------------------------
// Y(OxN) = W(OxCD) * X(CDxN).  FINAL: Yf = gamma*acc + resid (fp32), else bf16.
// 256 threads, 8 warps, double-buffered cp.async, K-stage = 32 (proven).
// TN=128 -> warps 2x4 (identical to the proven proj config); TN=64 -> 4x2.
template<int CD, int TO, int TN>
__device__ __forceinline__ void stage_tiles(const bf16* __restrict__ W,
                                            const bf16* __restrict__ Xb,
                                            bf16* As, bf16* Bs,
                                            int o0, int n0, int k0, int tid) {
    #pragma unroll
    for (int ch = tid; ch < TO * 4; ch += 256) {        // A: TOx32
        int r = ch >> 2, cc = (ch & 3) * 8;
        cpa16(As + r * 40 + cc, W + (size_t)(o0 + r) * CD + k0 + cc);
    }
    #pragma unroll
    for (int ch = tid; ch < 4 * TN; ch += 256) {        // B: 32xTN
        int r = ch / (TN / 8), cc = (ch % (TN / 8)) * 8;
        cpa16(Bs + r * (TN + 8) + cc, Xb + (size_t)(k0 + r) * NQd + n0 + cc);
    }
    cpa_commit();
}

template<bool FINAL, int CD, int TO, int TN>
__device__ __forceinline__ void gemm_core(const bf16* __restrict__ W,
                                          const bf16* __restrict__ Xb,
                                          bf16* __restrict__ Ybf,
                                          float* __restrict__ Yf,
                                          const float* __restrict__ resid,
                                          const float* __restrict__ gammap) {
    const int n0 = blockIdx.x * TN;
    const int o0 = blockIdx.y * TO;
    constexpr int ABUF = TO * 40;            // bf16 elems per A buffer
    constexpr int BBUF = 32 * (TN + 8);      // bf16 elems per B buffer
    constexpr int WRn  = (TN == 128) ? 2 : 4;    // warp-grid rows
    constexpr int WCn  = 8 / WRn;                // warp-grid cols
    constexpr int MI   = TO / (16 * WRn);        // row frags per warp
    constexpr int CSL  = TN + 4;                 // Cs stride (floats)

    extern __shared__ __align__(16) char smem_raw[];
    bf16*  AsB = (bf16*)smem_raw;                        // [2][ABUF]
    bf16*  BsB = (bf16*)(smem_raw + 2 * ABUF * 2);       // [2][BBUF]
    float* Cs  = (float*)smem_raw;                       // [TO*CSL] (reuse)

    const int tid  = threadIdx.x;
    const int warp = tid >> 5;
    const int wr   = warp / WCn;
    const int wc   = warp % WCn;

    wmma::fragment<wmma::accumulator,16,16,16,float> acc[MI][2];
    #pragma unroll
    for (int i = 0; i < MI; i++)
        #pragma unroll
        for (int j = 0; j < 2; j++) wmma::fill_fragment(acc[i][j], 0.0f);

    constexpr int KT = CD / 32;
    stage_tiles<CD, TO, TN>(W, Xb, AsB, BsB, o0, n0, 0, tid);

    for (int kt = 0; kt < KT; kt++) {
        if (kt + 1 < KT) {
            stage_tiles<CD, TO, TN>(W, Xb, AsB + ((kt + 1) & 1) * ABUF,
                                            BsB + ((kt + 1) & 1) * BBUF,
                                    o0, n0, (kt + 1) * 32, tid);
            asm volatile("cp.async.wait_group 1;\n" ::);
        } else {
            asm volatile("cp.async.wait_group 0;\n" ::);
        }
        __syncthreads();

        const bf16* As = AsB + (kt & 1) * ABUF;
        const bf16* Bs = BsB + (kt & 1) * BBUF;
        #pragma unroll
        for (int ks = 0; ks < 2; ks++) {
            wmma::fragment<wmma::matrix_a,16,16,16,bf16,wmma::row_major> af[MI];
            wmma::fragment<wmma::matrix_b,16,16,16,bf16,wmma::row_major> bg[2];
            #pragma unroll
            for (int i = 0; i < MI; i++)
                wmma::load_matrix_sync(af[i], As + (wr*(TO/WRn) + i*16) * 40 + ks*16, 40);
            #pragma unroll
            for (int j = 0; j < 2; j++)
                wmma::load_matrix_sync(bg[j], Bs + (ks*16) * (TN + 8) + wc*32 + j*16, TN + 8);
            #pragma unroll
            for (int i = 0; i < MI; i++)
                #pragma unroll
                for (int j = 0; j < 2; j++)
                    wmma::mma_sync(acc[i][j], af[i], bg[j], acc[i][j]);
        }
        __syncthreads();
    }

    // epilogue via Cs (smem reuse is safe: accum is in registers)
    #pragma unroll
    for (int i = 0; i < MI; i++)
        #pragma unroll
        for (int j = 0; j < 2; j++)
            wmma::store_matrix_sync(&Cs[(wr*(TO/WRn) + i*16) * CSL + wc*32 + j*16],
                                    acc[i][j], CSL, wmma::mem_row_major);
    __syncthreads();

    float g = 0.0f;
    if (FINAL) g = gammap[0];
    #pragma unroll
    for (int t = tid; t < TO * TN / 4; t += 256) {
        int r = t / (TN / 4), c4 = (t % (TN / 4)) * 4;
        float4 v = *(float4*)&Cs[r * CSL + c4];
        size_t gi = (size_t)(o0 + r) * NQd + n0 + c4;
        if (FINAL) {
            float4 x = *(const float4*)&resid[gi];
            v.x = g * v.x + x.x;  v.y = g * v.y + x.y;
            v.z = g * v.z + x.z;  v.w = g * v.w + x.w;
            *(float4*)&Yf[gi] = v;
        } else {
            __nv_bfloat162 two[2] = { __floats2bfloat162_rn(v.x, v.y),
                                      __floats2bfloat162_rn(v.z, v.w) };
            *(uint2*)&Ybf[gi] = *(uint2*)two;
        }
    }
}

// ---------------- Q/K/V projections: one launch, z = b*3 + which -----------
struct ProjArgs { const bf16* W[3]; const bf16* X[2]; bf16* Y[3]; };

__global__ void proj_kernel(ProjArgs a) {
    int z = blockIdx.z;
    int which = z % 3, b = z / 3;
    const bf16* W  = a.W[which];
    const bf16* Xb = (which == 0 ? a.X[0] : a.X[1]) + (size_t)b * CQd * NQd;
    bf16*       Yb = a.Y[which] + (size_t)b * ODd * NQd;
    gemm_core<false, CQd, 128, 128>(W, Xb, Yb, nullptr, nullptr, nullptr);
}

// ---------------- final: out = gamma * (W'_b @ Q_b) + x_q ------------------
// 64x64 tiles -> 512 CTAs (~3.5/SM): deeper MLP for the DRAM-bound epilogue.
__global__ void final_kernel(const float* __restrict__ xq,
                             const float* __restrict__ gammap,
                             float* __restrict__ out) {
    int b = blockIdx.z;
    gemm_core<true, ODd, 64, 64>(g_Wp + (size_t)b * CQd * ODd,
                                 g_Q  + (size_t)b * ODd * NQd,
                                 nullptr,
                                 out + (size_t)b * CQd * NQd,
                                 xq  + (size_t)b * CQd * NQd,
                                 gammap);
}

// ---------------- kv_outer: atomically accumulate K_h * V_h^T into g_Mf ----
// 256 CTAs (KSPLIT x NH x BATCH); epilogue = spread-address REDG (no return).
__global__ void kv_outer_kernel() {
    const int ks = blockIdx.x, h = blockIdx.y, b = blockIdx.z;
    const bf16* Kb = g_K + ((size_t)b * ODd + h * DKd) * NKVd;
    const bf16* Vb = g_V + ((size_t)b * ODd + h * DKd) * NKVd;
    const int tid = threadIdx.x;
    const int warp = tid >> 5, wr = warp >> 1, wc = warp & 1;
    __shared__ __align__(16) float Cs[64][68];

    wmma::fragment<wmma::accumulator,16,16,16,float> acc[2][2];
    #pragma unroll
    for (int i = 0; i < 2; i++)
        #pragma unroll
        for (int j = 0; j < 2; j++) wmma::fill_fragment(acc[i][j], 0.0f);

    const int k0 = ks * (NKVd / KSPLIT);
    for (int k = k0; k < k0 + NKVd / KSPLIT; k += 16) {
        wmma::fragment<wmma::matrix_a,16,16,16,bf16,wmma::row_major> af[2];
        wmma::fragment<wmma::matrix_b,16,16,16,bf16,wmma::col_major> bg[2];
        #pragma unroll
        for (int i = 0; i < 2; i++)
            wmma::load_matrix_sync(af[i], Kb + (size_t)(wr*32 + i*16) * NKVd + k, NKVd);
        #pragma unroll
        for (int j = 0; j < 2; j++)
            wmma::load_matrix_sync(bg[j], Vb + (size_t)(wc*32 + j*16) * NKVd + k, NKVd);
        #pragma unroll
        for (int i = 0; i < 2; i++)
            #pragma unroll
            for (int j = 0; j < 2; j++)
                wmma::mma_sync(acc[i][j], af[i], bg[j], acc[i][j]);
    }
    #pragma unroll
    for (int i = 0; i < 2; i++)
        #pragma unroll
        for (int j = 0; j < 2; j++)
            wmma::store_matrix_sync(&Cs[wr*32 + i*16][wc*32 + j*16], acc[i][j], 68,
                                    wmma::mem_row_major);
    __syncthreads();

    float* Mf = g_Mf + ((size_t)b * NH + h) * DKd * DKd;
    #pragma unroll
    for (int t = tid; t < 4096; t += 128)
        atomicAdd(&Mf[t], Cs[t >> 6][t & 63]);
}

// ---------------- womt: Wp_b[c, h*64+d] = sum_e Wo[c,h*64+e] * M~_bh[d,e] --
// M~ = g_Mf/64, scaled+converted while staging to smem.
__global__ void womt_kernel() {
    const int c0 = blockIdx.x * 64, h = blockIdx.y, b = blockIdx.z;
    __shared__ __align__(16) float Cs[64][68];
    __shared__ __align__(16) bf16  Msh[64][72];
    const int tid = threadIdx.x;
    const int warp = tid >> 5, wr = warp >> 1, wc = warp & 1;

    const float* Mf = g_Mf + ((size_t)b * NH + h) * DKd * DKd;
    const float sc = 1.0f / DKd;
    #pragma unroll
    for (int t = tid; t < 1024; t += 128) {   // 4-wide chunks of 4096 floats
        int r = t >> 4, c4 = (t & 15) * 4;
        float4 v = *(const float4*)&Mf[(size_t)r * DKd + c4];
        __nv_bfloat162 two[2] = { __floats2bfloat162_rn(v.x * sc, v.y * sc),
                                  __floats2bfloat162_rn(v.z * sc, v.w * sc) };
        *(uint2*)&Msh[r][c4] = *(uint2*)two;
    }
    __syncthreads();

    wmma::fragment<wmma::accumulator,16,16,16,float> acc[2][2];
    #pragma unroll
    for (int i = 0; i < 2; i++)
        #pragma unroll
        for (int j = 0; j < 2; j++) wmma::fill_fragment(acc[i][j], 0.0f);

    #pragma unroll
    for (int kt = 0; kt < 4; kt++) {
        wmma::fragment<wmma::matrix_a,16,16,16,bf16,wmma::row_major> af[2];
        wmma::fragment<wmma::matrix_b,16,16,16,bf16,wmma::col_major> bg[2];
        #pragma unroll
        for (int i = 0; i < 2; i++)
            wmma::load_matrix_sync(af[i],
                g_Wo + (size_t)(c0 + wr*32 + i*16) * ODd + h * DKd + kt*16, ODd);
        #pragma unroll
        for (int j = 0; j < 2; j++)   // B(e,d) = M~[d,e] -> col_major ldm 72
            wmma::load_matrix_sync(bg[j], &Msh[wc*32 + j*16][kt*16], 72);
        #pragma unroll
        for (int i = 0; i < 2; i++)
            #pragma unroll
            for (int j = 0; j < 2; j++)
                wmma::mma_sync(acc[i][j], af[i], bg[j], acc[i][j]);
    }
    #pragma unroll
    for (int i = 0; i < 2; i++)
        #pragma unroll
        for (int j = 0; j < 2; j++)
            wmma::store_matrix_sync(&Cs[wr*32 + i*16][wc*32 + j*16], acc[i][j], 68,
                                    wmma::mem_row_major);
    __syncthreads();

    bf16* outp = g_Wp + (size_t)b * CQd * ODd;
    #pragma unroll
    for (int t = tid; t < 1024; t += 128) {   // 64x64, 4-wide
        int r = t >> 4, c4 = (t & 15) * 4;
        float4 v = *(float4*)&Cs[r][c4];
        __nv_bfloat162 two[2] = { __floats2bfloat162_rn(v.x, v.y),
                                  __floats2bfloat162_rn(v.z, v.w) };
        *(uint2*)&outp[(size_t)(c0 + r) * ODd + h * DKd + c4] = *(uint2*)two;
    }
}

// ---------------------------------------------------------------------------
extern "C" void kernel_launch(void* const* d_in, const int* in_sizes, int n_in,
                              void* d_out, int out_size) {
    const float* xq    = (const float*)d_in[0];
    const float* xkv   = (const float*)d_in[1];
    const float* Wq    = (const float*)d_in[2];
    const float* Wk    = (const float*)d_in[3];
    const float* Wv    = (const float*)d_in[4];
    const float* Wo    = (const float*)d_in[5];
    const float* gamma = (const float*)d_in[6];
    float* out = (float*)d_out;

    cudaFuncSetAttribute(proj_kernel,  cudaFuncAttributeMaxDynamicSharedMemorySize, 69632);
    cudaFuncSetAttribute(final_kernel, cudaFuncAttributeMaxDynamicSharedMemorySize, 20480);

    // 1) convert everything to bf16 + zero g_Mf (one launch)
    convert_all_kernel<<<4608, 256>>>(xq, xkv, Wq, Wk, Wv, Wo);

    // 2) Q/K/V projections (one launch, z = b*3 + which)
    ProjArgs pa;
    void *p;
    cudaGetSymbolAddress(&p, g_Wq);  pa.W[0] = (const bf16*)p;
    cudaGetSymbolAddress(&p, g_Wk);  pa.W[1] = (const bf16*)p;
    cudaGetSymbolAddress(&p, g_Wv);  pa.W[2] = (const bf16*)p;
    cudaGetSymbolAddress(&p, g_xq);  pa.X[0] = (const bf16*)p;
    cudaGetSymbolAddress(&p, g_xkv); pa.X[1] = (const bf16*)p;
    cudaGetSymbolAddress(&p, g_Q);   pa.Y[0] = (bf16*)p;
    cudaGetSymbolAddress(&p, g_K);   pa.Y[1] = (bf16*)p;
    cudaGetSymbolAddress(&p, g_V);   pa.Y[2] = (bf16*)p;
    proj_kernel<<<dim3(NQd/128, ODd/128, BATCH*3), 256, 67584>>>(pa);

    // 3) M accumulated via REDG (no reduce kernel), then womt
    kv_outer_kernel<<<dim3(KSPLIT, NH, BATCH), 128>>>();
    womt_kernel<<<dim3(CQd/64, NH, BATCH), 128>>>();

    // 4) out = gamma * (Wp_b @ Q_b) + x_q
    final_kernel<<<dim3(NQd/64, CQd/64, BATCH), 256, 19456>>>(xq, gamma, out);
}

// round 15
// speedup vs baseline: 1.0113x; 1.0113x over previous
#include <cuda_runtime.h>
#include <cuda_bf16.h>
#include <mma.h>
#include <cstdint>
#include <cstddef>

using namespace nvcuda;
typedef __nv_bfloat16 bf16;

#define BATCH 4
#define CQd   256
#define NQd   2048
#define NKVd  2048
#define NH    8
#define DKd   64
#define ODd   512   // NH*DKd
#define KSPLIT 8

// ---------------- scratch (static device globals; no runtime alloc) -------
__device__ __align__(16) bf16 g_xq [BATCH*CQd*NQd];
__device__ __align__(16) bf16 g_xkv[BATCH*CQd*NKVd];
__device__ __align__(16) bf16 g_Wq [ODd*CQd];
__device__ __align__(16) bf16 g_Wk [ODd*CQd];
__device__ __align__(16) bf16 g_Wv [ODd*CQd];
__device__ __align__(16) bf16 g_Wo [CQd*ODd];
__device__ __align__(16) bf16 g_Q  [BATCH*ODd*NQd];
__device__ __align__(16) bf16 g_K  [BATCH*ODd*NKVd];
__device__ __align__(16) bf16 g_V  [BATCH*ODd*NKVd];
__device__ __align__(16) float g_Mf [BATCH*NH*DKd*DKd];   // atomically accumulated K^T V
__device__ __align__(16) bf16 g_Wp [BATCH*CQd*ODd];       // fused Wo @ blockdiag(M^T)

// ---------------- fused fp32 -> bf16 conversion + g_Mf zeroing -------------
__global__ void convert_all_kernel(const float* __restrict__ xq,
                                   const float* __restrict__ xkv,
                                   const float* __restrict__ Wq,
                                   const float* __restrict__ Wk,
                                   const float* __restrict__ Wv,
                                   const float* __restrict__ Wo) {
    int i = blockIdx.x * blockDim.x + threadIdx.x;  // float4 index, total 1179648
    // fold the g_Mf zeroing into spare work here (g_Mf = 131072 floats = 32768 float4)
    if (i < 32768) ((float4*)g_Mf)[i] = make_float4(0.f, 0.f, 0.f, 0.f);

    const float* src; bf16* dst; int off;
    if (i < 524288)            { src = xq;  dst = g_xq;  off = i; }
    else if (i < 1048576)      { src = xkv; dst = g_xkv; off = i - 524288; }
    else {
        int j = i - 1048576;
        int w = j >> 15;  off = j & 32767;
        src = (w == 0) ? Wq : (w == 1) ? Wk : (w == 2) ? Wv : Wo;
        dst = (w == 0) ? g_Wq : (w == 1) ? g_Wk : (w == 2) ? g_Wv : g_Wo;
    }
    float4 v = ((const float4*)src)[off];
    __nv_bfloat162 two[2] = { __floats2bfloat162_rn(v.x, v.y),
                              __floats2bfloat162_rn(v.z, v.w) };
    *(uint2*)&dst[(size_t)off * 4] = *(uint2*)two;
}

// ---------------- cp.async helpers -----------------------------------------
__device__ __forceinline__ void cpa16(void* dst, const void* src) {
    unsigned int d = (unsigned int)__cvta_generic_to_shared(dst);
    asm volatile("cp.async.cg.shared.global [%0], [%1], 16;\n" :: "r"(d), "l"(src));
}
__device__ __forceinline__ void cpa_commit() {
    asm volatile("cp.async.commit_group;\n" ::);
}

// ---------------- pipelined TOxTNx32 bf16 GEMM core ------------------------
// Y(OxN) = W(OxCD) * X(CDxN).  FINAL: Yf = gamma*acc + resid (fp32), else bf16.
// 256 threads, 8 warps, double-buffered cp.async, K-stage = 32 (proven).
// TN=128 -> warps 2x4 (identical to the proven proj config); TN=64 -> 4x2.
template<int CD, int TO, int TN>
__device__ __forceinline__ void stage_tiles(const bf16* __restrict__ W,
                                            const bf16* __restrict__ Xb,
                                            bf16* As, bf16* Bs,
                                            int o0, int n0, int k0, int tid) {
    #pragma unroll
    for (int ch = tid; ch < TO * 4; ch += 256) {        // A: TOx32
        int r = ch >> 2, cc = (ch & 3) * 8;
        cpa16(As + r * 40 + cc, W + (size_t)(o0 + r) * CD + k0 + cc);
    }
    #pragma unroll
    for (int ch = tid; ch < 4 * TN; ch += 256) {        // B: 32xTN
        int r = ch / (TN / 8), cc = (ch % (TN / 8)) * 8;
        cpa16(Bs + r * (TN + 8) + cc, Xb + (size_t)(k0 + r) * NQd + n0 + cc);
    }
    cpa_commit();
}

template<bool FINAL, int CD, int TO, int TN>
__device__ __forceinline__ void gemm_core(const bf16* __restrict__ W,
                                          const bf16* __restrict__ Xb,
                                          bf16* __restrict__ Ybf,
                                          float* __restrict__ Yf,
                                          const float* __restrict__ resid,
                                          const float* __restrict__ gammap) {
    const int n0 = blockIdx.x * TN;
    const int o0 = blockIdx.y * TO;
    constexpr int ABUF = TO * 40;            // bf16 elems per A buffer
    constexpr int BBUF = 32 * (TN + 8);      // bf16 elems per B buffer
    constexpr int WRn  = (TN == 128) ? 2 : 4;    // warp-grid rows
    constexpr int WCn  = 8 / WRn;                // warp-grid cols
    constexpr int MI   = TO / (16 * WRn);        // row frags per warp
    constexpr int CSL  = TN + 4;                 // Cs stride (floats)

    extern __shared__ __align__(16) char smem_raw[];
    bf16*  AsB = (bf16*)smem_raw;                        // [2][ABUF]
    bf16*  BsB = (bf16*)(smem_raw + 2 * ABUF * 2);       // [2][BBUF]
    float* Cs  = (float*)smem_raw;                       // [TO*CSL] (reuse)

    const int tid  = threadIdx.x;
    const int warp = tid >> 5;
    const int wr   = warp / WCn;
    const int wc   = warp % WCn;

    wmma::fragment<wmma::accumulator,16,16,16,float> acc[MI][2];
    #pragma unroll
    for (int i = 0; i < MI; i++)
        #pragma unroll
        for (int j = 0; j < 2; j++) wmma::fill_fragment(acc[i][j], 0.0f);

    constexpr int KT = CD / 32;
    stage_tiles<CD, TO, TN>(W, Xb, AsB, BsB, o0, n0, 0, tid);

    for (int kt = 0; kt < KT; kt++) {
        if (kt + 1 < KT) {
            stage_tiles<CD, TO, TN>(W, Xb, AsB + ((kt + 1) & 1) * ABUF,
                                            BsB + ((kt + 1) & 1) * BBUF,
                                    o0, n0, (kt + 1) * 32, tid);
            asm volatile("cp.async.wait_group 1;\n" ::);
        } else {
            asm volatile("cp.async.wait_group 0;\n" ::);
        }
        __syncthreads();

        const bf16* As = AsB + (kt & 1) * ABUF;
        const bf16* Bs = BsB + (kt & 1) * BBUF;
        #pragma unroll
        for (int ks = 0; ks < 2; ks++) {
            wmma::fragment<wmma::matrix_a,16,16,16,bf16,wmma::row_major> af[MI];
            wmma::fragment<wmma::matrix_b,16,16,16,bf16,wmma::row_major> bg[2];
            #pragma unroll
            for (int i = 0; i < MI; i++)
                wmma::load_matrix_sync(af[i], As + (wr*(TO/WRn) + i*16) * 40 + ks*16, 40);
            #pragma unroll
            for (int j = 0; j < 2; j++)
                wmma::load_matrix_sync(bg[j], Bs + (ks*16) * (TN + 8) + wc*32 + j*16, TN + 8);
            #pragma unroll
            for (int i = 0; i < MI; i++)
                #pragma unroll
                for (int j = 0; j < 2; j++)
                    wmma::mma_sync(acc[i][j], af[i], bg[j], acc[i][j]);
        }
        __syncthreads();
    }

    // epilogue via Cs (smem reuse is safe: accum is in registers)
    #pragma unroll
    for (int i = 0; i < MI; i++)
        #pragma unroll
        for (int j = 0; j < 2; j++)
            wmma::store_matrix_sync(&Cs[(wr*(TO/WRn) + i*16) * CSL + wc*32 + j*16],
                                    acc[i][j], CSL, wmma::mem_row_major);
    __syncthreads();

    float g = 0.0f;
    if (FINAL) g = gammap[0];
    #pragma unroll
    for (int t = tid; t < TO * TN / 4; t += 256) {
        int r = t / (TN / 4), c4 = (t % (TN / 4)) * 4;
        float4 v = *(float4*)&Cs[r * CSL + c4];
        size_t gi = (size_t)(o0 + r) * NQd + n0 + c4;
        if (FINAL) {
            float4 x = *(const float4*)&resid[gi];
            v.x = g * v.x + x.x;  v.y = g * v.y + x.y;
            v.z = g * v.z + x.z;  v.w = g * v.w + x.w;
            *(float4*)&Yf[gi] = v;
        } else {
            __nv_bfloat162 two[2] = { __floats2bfloat162_rn(v.x, v.y),
                                      __floats2bfloat162_rn(v.z, v.w) };
            *(uint2*)&Ybf[gi] = *(uint2*)two;
        }
    }
}

// ---------------- Q/K/V projections: one launch, z = b*3 + which -----------
struct ProjArgs { const bf16* W[3]; const bf16* X[2]; bf16* Y[3]; };

__global__ void proj_kernel(ProjArgs a) {
    int z = blockIdx.z;
    int which = z % 3, b = z / 3;
    const bf16* W  = a.W[which];
    const bf16* Xb = (which == 0 ? a.X[0] : a.X[1]) + (size_t)b * CQd * NQd;
    bf16*       Yb = a.Y[which] + (size_t)b * ODd * NQd;
    gemm_core<false, CQd, 128, 128>(W, Xb, Yb, nullptr, nullptr, nullptr);
}

// ---------------- final: out = gamma * (W'_b @ Q_b) + x_q ------------------
// 64x64 tiles -> 512 CTAs (~3.5/SM): deeper MLP for the DRAM-bound epilogue.
__global__ void final_kernel(const float* __restrict__ xq,
                             const float* __restrict__ gammap,
                             float* __restrict__ out) {
    int b = blockIdx.z;
    gemm_core<true, ODd, 64, 64>(g_Wp + (size_t)b * CQd * ODd,
                                 g_Q  + (size_t)b * ODd * NQd,
                                 nullptr,
                                 out + (size_t)b * CQd * NQd,
                                 xq  + (size_t)b * CQd * NQd,
                                 gammap);
}

// ---------------- kv_outer: atomically accumulate K_h * V_h^T into g_Mf ----
// 256 CTAs (KSPLIT x NH x BATCH); epilogue = spread-address REDG (no return).
__global__ void kv_outer_kernel() {
    const int ks = blockIdx.x, h = blockIdx.y, b = blockIdx.z;
    const bf16* Kb = g_K + ((size_t)b * ODd + h * DKd) * NKVd;
    const bf16* Vb = g_V + ((size_t)b * ODd + h * DKd) * NKVd;
    const int tid = threadIdx.x;
    const int warp = tid >> 5, wr = warp >> 1, wc = warp & 1;
    __shared__ __align__(16) float Cs[64][68];

    wmma::fragment<wmma::accumulator,16,16,16,float> acc[2][2];
    #pragma unroll
    for (int i = 0; i < 2; i++)
        #pragma unroll
        for (int j = 0; j < 2; j++) wmma::fill_fragment(acc[i][j], 0.0f);

    const int k0 = ks * (NKVd / KSPLIT);
    for (int k = k0; k < k0 + NKVd / KSPLIT; k += 16) {
        wmma::fragment<wmma::matrix_a,16,16,16,bf16,wmma::row_major> af[2];
        wmma::fragment<wmma::matrix_b,16,16,16,bf16,wmma::col_major> bg[2];
        #pragma unroll
        for (int i = 0; i < 2; i++)
            wmma::load_matrix_sync(af[i], Kb + (size_t)(wr*32 + i*16) * NKVd + k, NKVd);
        #pragma unroll
        for (int j = 0; j < 2; j++)
            wmma::load_matrix_sync(bg[j], Vb + (size_t)(wc*32 + j*16) * NKVd + k, NKVd);
        #pragma unroll
        for (int i = 0; i < 2; i++)
            #pragma unroll
            for (int j = 0; j < 2; j++)
                wmma::mma_sync(acc[i][j], af[i], bg[j], acc[i][j]);
    }
    #pragma unroll
    for (int i = 0; i < 2; i++)
        #pragma unroll
        for (int j = 0; j < 2; j++)
            wmma::store_matrix_sync(&Cs[wr*32 + i*16][wc*32 + j*16], acc[i][j], 68,
                                    wmma::mem_row_major);
    __syncthreads();

    float* Mf = g_Mf + ((size_t)b * NH + h) * DKd * DKd;
    #pragma unroll
    for (int t = tid; t < 4096; t += 128)
        atomicAdd(&Mf[t], Cs[t >> 6][t & 63]);
}

// ---------------- womt: Wp_b[c, h*64+d] = sum_e Wo[c,h*64+e] * M~_bh[d,e] --
// M~ = g_Mf/64, scaled+converted while staging to smem.
__global__ void womt_kernel() {
    const int c0 = blockIdx.x * 64, h = blockIdx.y, b = blockIdx.z;
    __shared__ __align__(16) float Cs[64][68];
    __shared__ __align__(16) bf16  Msh[64][72];
    const int tid = threadIdx.x;
    const int warp = tid >> 5, wr = warp >> 1, wc = warp & 1;

    const float* Mf = g_Mf + ((size_t)b * NH + h) * DKd * DKd;
    const float sc = 1.0f / DKd;
    #pragma unroll
    for (int t = tid; t < 1024; t += 128) {   // 4-wide chunks of 4096 floats
        int r = t >> 4, c4 = (t & 15) * 4;
        float4 v = *(const float4*)&Mf[(size_t)r * DKd + c4];
        __nv_bfloat162 two[2] = { __floats2bfloat162_rn(v.x * sc, v.y * sc),
                                  __floats2bfloat162_rn(v.z * sc, v.w * sc) };
        *(uint2*)&Msh[r][c4] = *(uint2*)two;
    }
    __syncthreads();

    wmma::fragment<wmma::accumulator,16,16,16,float> acc[2][2];
    #pragma unroll
    for (int i = 0; i < 2; i++)
        #pragma unroll
        for (int j = 0; j < 2; j++) wmma::fill_fragment(acc[i][j], 0.0f);

    #pragma unroll
    for (int kt = 0; kt < 4; kt++) {
        wmma::fragment<wmma::matrix_a,16,16,16,bf16,wmma::row_major> af[2];
        wmma::fragment<wmma::matrix_b,16,16,16,bf16,wmma::col_major> bg[2];
        #pragma unroll
        for (int i = 0; i < 2; i++)
            wmma::load_matrix_sync(af[i],
                g_Wo + (size_t)(c0 + wr*32 + i*16) * ODd + h * DKd + kt*16, ODd);
        #pragma unroll
        for (int j = 0; j < 2; j++)   // B(e,d) = M~[d,e] -> col_major ldm 72
            wmma::load_matrix_sync(bg[j], &Msh[wc*32 + j*16][kt*16], 72);
        #pragma unroll
        for (int i = 0; i < 2; i++)
            #pragma unroll
            for (int j = 0; j < 2; j++)
                wmma::mma_sync(acc[i][j], af[i], bg[j], acc[i][j]);
    }
    #pragma unroll
    for (int i = 0; i < 2; i++)
        #pragma unroll
        for (int j = 0; j < 2; j++)
            wmma::store_matrix_sync(&Cs[wr*32 + i*16][wc*32 + j*16], acc[i][j], 68,
                                    wmma::mem_row_major);
    __syncthreads();

    bf16* outp = g_Wp + (size_t)b * CQd * ODd;
    #pragma unroll
    for (int t = tid; t < 1024; t += 128) {   // 64x64, 4-wide
        int r = t >> 4, c4 = (t & 15) * 4;
        float4 v = *(float4*)&Cs[r][c4];
        __nv_bfloat162 two[2] = { __floats2bfloat162_rn(v.x, v.y),
                                  __floats2bfloat162_rn(v.z, v.w) };
        *(uint2*)&outp[(size_t)(c0 + r) * ODd + h * DKd + c4] = *(uint2*)two;
    }
}

// ---------------------------------------------------------------------------
extern "C" void kernel_launch(void* const* d_in, const int* in_sizes, int n_in,
                              void* d_out, int out_size) {
    const float* xq    = (const float*)d_in[0];
    const float* xkv   = (const float*)d_in[1];
    const float* Wq    = (const float*)d_in[2];
    const float* Wk    = (const float*)d_in[3];
    const float* Wv    = (const float*)d_in[4];
    const float* Wo    = (const float*)d_in[5];
    const float* gamma = (const float*)d_in[6];
    float* out = (float*)d_out;

    cudaFuncSetAttribute(proj_kernel,  cudaFuncAttributeMaxDynamicSharedMemorySize, 69632);
    cudaFuncSetAttribute(final_kernel, cudaFuncAttributeMaxDynamicSharedMemorySize, 20480);

    // 1) convert everything to bf16 + zero g_Mf (one launch)
    convert_all_kernel<<<4608, 256>>>(xq, xkv, Wq, Wk, Wv, Wo);

    // 2) Q/K/V projections (one launch, z = b*3 + which)
    ProjArgs pa;
    void *p;
    cudaGetSymbolAddress(&p, g_Wq);  pa.W[0] = (const bf16*)p;
    cudaGetSymbolAddress(&p, g_Wk);  pa.W[1] = (const bf16*)p;
    cudaGetSymbolAddress(&p, g_Wv);  pa.W[2] = (const bf16*)p;
    cudaGetSymbolAddress(&p, g_xq);  pa.X[0] = (const bf16*)p;
    cudaGetSymbolAddress(&p, g_xkv); pa.X[1] = (const bf16*)p;
    cudaGetSymbolAddress(&p, g_Q);   pa.Y[0] = (bf16*)p;
    cudaGetSymbolAddress(&p, g_K);   pa.Y[1] = (bf16*)p;
    cudaGetSymbolAddress(&p, g_V);   pa.Y[2] = (bf16*)p;
    proj_kernel<<<dim3(NQd/128, ODd/128, BATCH*3), 256, 67584>>>(pa);

    // 3) M accumulated via REDG (no reduce kernel), then womt
    kv_outer_kernel<<<dim3(KSPLIT, NH, BATCH), 128>>>();
    womt_kernel<<<dim3(CQd/64, NH, BATCH), 128>>>();

    // 4) out = gamma * (Wp_b @ Q_b) + x_q
    final_kernel<<<dim3(NQd/64, CQd/64, BATCH), 256, 19456>>>(xq, gamma, out);
}

// round 16
// speedup vs baseline: 1.0453x; 1.0336x over previous
#include <cuda_runtime.h>
#include <cuda_bf16.h>
#include <mma.h>
#include <cstdint>
#include <cstddef>

using namespace nvcuda;
typedef __nv_bfloat16 bf16;

#define BATCH 4
#define CQd   256
#define NQd   2048
#define NKVd  2048
#define NH    8
#define DKd   64
#define ODd   512   // NH*DKd
#define KSPLIT 8

// ---------------- scratch (static device globals; no runtime alloc) -------
__device__ __align__(16) bf16 g_xq [BATCH*CQd*NQd];
__device__ __align__(16) bf16 g_xkv[BATCH*CQd*NKVd];
__device__ __align__(16) bf16 g_Wq [ODd*CQd];
__device__ __align__(16) bf16 g_Wk [ODd*CQd];
__device__ __align__(16) bf16 g_Wv [ODd*CQd];
__device__ __align__(16) bf16 g_Wo [CQd*ODd];
__device__ __align__(16) bf16 g_Q  [BATCH*ODd*NQd];
__device__ __align__(16) bf16 g_K  [BATCH*ODd*NKVd];
__device__ __align__(16) bf16 g_V  [BATCH*ODd*NKVd];
__device__ __align__(16) float g_Mpart[KSPLIT*BATCH*NH*DKd*DKd];
__device__ __align__(16) bf16 g_M  [BATCH*NH*DKd*DKd];
__device__ __align__(16) bf16 g_Wp [BATCH*CQd*ODd];   // fused Wo @ blockdiag(M^T)

// ---------------- fused fp32 -> bf16 conversion (all 6 tensors) -----------
__global__ void convert_all_kernel(const float* __restrict__ xq,
                                   const float* __restrict__ xkv,
                                   const float* __restrict__ Wq,
                                   const float* __restrict__ Wk,
                                   const float* __restrict__ Wv,
                                   const float* __restrict__ Wo) {
    int i = blockIdx.x * blockDim.x + threadIdx.x;  // float4 index, total 1179648
    const float* src; bf16* dst; int off;
    if (i < 524288)            { src = xq;  dst = g_xq;  off = i; }
    else if (i < 1048576)      { src = xkv; dst = g_xkv; off = i - 524288; }
    else {
        int j = i - 1048576;
        int w = j >> 15;  off = j & 32767;
        src = (w == 0) ? Wq : (w == 1) ? Wk : (w == 2) ? Wv : Wo;
        dst = (w == 0) ? g_Wq : (w == 1) ? g_Wk : (w == 2) ? g_Wv : g_Wo;
    }
    float4 v = ((const float4*)src)[off];
    __nv_bfloat162 two[2] = { __floats2bfloat162_rn(v.x, v.y),
                              __floats2bfloat162_rn(v.z, v.w) };
    *(uint2*)&dst[(size_t)off * 4] = *(uint2*)two;
}

// ---------------- cp.async helpers -----------------------------------------
__device__ __forceinline__ void cpa16(void* dst, const void* src) {
    unsigned int d = (unsigned int)__cvta_generic_to_shared(dst);
    asm volatile("cp.async.cg.shared.global [%0], [%1], 16;\n" :: "r"(d), "l"(src));
}
__device__ __forceinline__ void cpa_commit() {
    asm volatile("cp.async.commit_group;\n" ::);
}

// ---------------- pipelined TOx128x32 bf16 GEMM core -----------------------
// Y(OxN) = W(OxCD) * X(CDxN).  FINAL: Yf = gamma*acc + resid (fp32), else bf16.
// 256 threads, 8 warps (2x4), warp tile (TO/2)x32, double-buffered cp.async,
// K-stage = 32 (the proven config).
template<int CD, int TO>
__device__ __forceinline__ void stage_tiles(const bf16* __restrict__ W,
                                            const bf16* __restrict__ Xb,
                                            bf16* As, bf16* Bs,
                                            int o0, int n0, int k0, int tid) {
    #pragma unroll
    for (int ch = tid; ch < TO * 4; ch += 256) {   // A: TOx32
        int r = ch >> 2, cc = (ch & 3) * 8;
        cpa16(As + r * 40 + cc, W + (size_t)(o0 + r) * CD + k0 + cc);
    }
    #pragma unroll
    for (int ch = tid; ch < 512; ch += 256) {      // B: 32x128
        int r = ch >> 4, cc = (ch & 15) * 8;
        cpa16(Bs + r * 136 + cc, Xb + (size_t)(k0 + r) * NQd + n0 + cc);
    }
    cpa_commit();
}

template<bool FINAL, int CD, int TO>
__device__ __forceinline__ void gemm_core(const bf16* __restrict__ W,
                                          const bf16* __restrict__ Xb,
                                          bf16* __restrict__ Ybf,
                                          float* __restrict__ Yf,
                                          const float* __restrict__ resid,
                                          const float* __restrict__ gammap) {
    const int n0 = blockIdx.x * 128;
    const int o0 = blockIdx.y * TO;
    constexpr int ABUF = TO * 40;        // bf16 elems per A buffer
    constexpr int BBUF = 32 * 136;       // bf16 elems per B buffer
    constexpr int MI   = TO / 32;        // row frags per warp

    extern __shared__ __align__(16) char smem_raw[];
    bf16*  AsB = (bf16*)smem_raw;                        // [2][ABUF]
    bf16*  BsB = (bf16*)(smem_raw + 2 * ABUF * 2);       // [2][BBUF]
    float* Cs  = (float*)smem_raw;                       // [TO*132] (reuse)

    const int tid  = threadIdx.x;
    const int warp = tid >> 5;
    const int wr   = warp >> 2;   // 0..1 (row half)
    const int wc   = warp & 3;    // 0..3 (32-col quarter)

    wmma::fragment<wmma::accumulator,16,16,16,float> acc[MI][2];
    #pragma unroll
    for (int i = 0; i < MI; i++)
        #pragma unroll
        for (int j = 0; j < 2; j++) wmma::fill_fragment(acc[i][j], 0.0f);

    constexpr int KT = CD / 32;
    stage_tiles<CD, TO>(W, Xb, AsB, BsB, o0, n0, 0, tid);

    for (int kt = 0; kt < KT; kt++) {
        if (kt + 1 < KT) {
            stage_tiles<CD, TO>(W, Xb, AsB + ((kt + 1) & 1) * ABUF,
                                        BsB + ((kt + 1) & 1) * BBUF,
                                o0, n0, (kt + 1) * 32, tid);
            asm volatile("cp.async.wait_group 1;\n" ::);
        } else {
            asm volatile("cp.async.wait_group 0;\n" ::);
        }
        __syncthreads();

        const bf16* As = AsB + (kt & 1) * ABUF;
        const bf16* Bs = BsB + (kt & 1) * BBUF;
        #pragma unroll
        for (int ks = 0; ks < 2; ks++) {
            wmma::fragment<wmma::matrix_a,16,16,16,bf16,wmma::row_major> af[MI];
            wmma::fragment<wmma::matrix_b,16,16,16,bf16,wmma::row_major> bg[2];
            #pragma unroll
            for (int i = 0; i < MI; i++)
                wmma::load_matrix_sync(af[i], As + (wr*(TO/2) + i*16) * 40 + ks*16, 40);
            #pragma unroll
            for (int j = 0; j < 2; j++)
                wmma::load_matrix_sync(bg[j], Bs + (ks*16) * 136 + wc*32 + j*16, 136);
            #pragma unroll
            for (int i = 0; i < MI; i++)
                #pragma unroll
                for (int j = 0; j < 2; j++)
                    wmma::mma_sync(acc[i][j], af[i], bg[j], acc[i][j]);
        }
        __syncthreads();
    }

    // epilogue via Cs (smem reuse is safe: accum is in registers)
    #pragma unroll
    for (int i = 0; i < MI; i++)
        #pragma unroll
        for (int j = 0; j < 2; j++)
            wmma::store_matrix_sync(&Cs[(wr*(TO/2) + i*16) * 132 + wc*32 + j*16],
                                    acc[i][j], 132, wmma::mem_row_major);
    __syncthreads();

    float g = 0.0f;
    if (FINAL) g = gammap[0];
    #pragma unroll
    for (int t = tid; t < TO * 32; t += 256) {   // TOx128 / 4-wide
        int r = t >> 5, c4 = (t & 31) * 4;
        float4 v = *(float4*)&Cs[r * 132 + c4];
        size_t gi = (size_t)(o0 + r) * NQd + n0 + c4;
        if (FINAL) {
            float4 x = *(const float4*)&resid[gi];
            v.x = g * v.x + x.x;  v.y = g * v.y + x.y;
            v.z = g * v.z + x.z;  v.w = g * v.w + x.w;
            *(float4*)&Yf[gi] = v;
        } else {
            __nv_bfloat162 two[2] = { __floats2bfloat162_rn(v.x, v.y),
                                      __floats2bfloat162_rn(v.z, v.w) };
            *(uint2*)&Ybf[gi] = *(uint2*)two;
        }
    }
}

// ---------------- Q/K/V projections: one launch, z = b*3 + which -----------
struct ProjArgs { const bf16* W[3]; const bf16* X[2]; bf16* Y[3]; };

__global__ void proj_kernel(ProjArgs a) {
    int z = blockIdx.z;
    int which = z % 3, b = z / 3;
    const bf16* W  = a.W[which];
    const bf16* Xb = (which == 0 ? a.X[0] : a.X[1]) + (size_t)b * CQd * NQd;
    bf16*       Yb = a.Y[which] + (size_t)b * ODd * NQd;
    gemm_core<false, CQd, 128>(W, Xb, Yb, nullptr, nullptr, nullptr);
}

// ---------------- final: out = gamma * (W'_b @ Q_b) + x_q ------------------
// TO=64 -> 256 CTAs (measured 20.3us vs 26.6us at TO=128).
__global__ void final_kernel(const float* __restrict__ xq,
                             const float* __restrict__ gammap,
                             float* __restrict__ out) {
    int b = blockIdx.z;
    gemm_core<true, ODd, 64>(g_Wp + (size_t)b * CQd * ODd,
                             g_Q  + (size_t)b * ODd * NQd,
                             nullptr,
                             out + (size_t)b * CQd * NQd,
                             xq  + (size_t)b * CQd * NQd,
                             gammap);
}

// ---------------- M_part[ks,b,h] = K_h(64 x Kslice) * V_h^T ----------------
// 256 CTAs (KSPLIT x NH x BATCH) — the R3-proven parallel shape.
__global__ void kv_outer_kernel() {
    const int ks = blockIdx.x, h = blockIdx.y, b = blockIdx.z;
    const bf16* Kb = g_K + ((size_t)b * ODd + h * DKd) * NKVd;
    const bf16* Vb = g_V + ((size_t)b * ODd + h * DKd) * NKVd;
    const int warp = threadIdx.x >> 5, wr = warp >> 1, wc = warp & 1;

    wmma::fragment<wmma::accumulator,16,16,16,float> acc[2][2];
    #pragma unroll
    for (int i = 0; i < 2; i++)
        #pragma unroll
        for (int j = 0; j < 2; j++) wmma::fill_fragment(acc[i][j], 0.0f);

    const int k0 = ks * (NKVd / KSPLIT);
    for (int k = k0; k < k0 + NKVd / KSPLIT; k += 16) {
        wmma::fragment<wmma::matrix_a,16,16,16,bf16,wmma::row_major> af[2];
        wmma::fragment<wmma::matrix_b,16,16,16,bf16,wmma::col_major> bg[2];
        #pragma unroll
        for (int i = 0; i < 2; i++)
            wmma::load_matrix_sync(af[i], Kb + (size_t)(wr*32 + i*16) * NKVd + k, NKVd);
        #pragma unroll
        for (int j = 0; j < 2; j++)
            wmma::load_matrix_sync(bg[j], Vb + (size_t)(wc*32 + j*16) * NKVd + k, NKVd);
        #pragma unroll
        for (int i = 0; i < 2; i++)
            #pragma unroll
            for (int j = 0; j < 2; j++)
                wmma::mma_sync(acc[i][j], af[i], bg[j], acc[i][j]);
    }
    float* Mout = g_Mpart + ((size_t)(ks * BATCH + b) * NH + h) * DKd * DKd;
    #pragma unroll
    for (int i = 0; i < 2; i++)
        #pragma unroll
        for (int j = 0; j < 2; j++)
            wmma::store_matrix_sync(Mout + (size_t)(wr*32 + i*16) * DKd + wc*32 + j*16,
                                    acc[i][j], DKd, wmma::mem_row_major);
}

// ---------------- reduce split-K partials (float4), scale, -> bf16 ---------
__global__ void reduce_m_kernel() {
    int i = blockIdx.x * blockDim.x + threadIdx.x;   // float4 index
    const int n4 = BATCH * NH * DKd * DKd / 4;       // 32768
    if (i >= n4) return;
    const float4* src = (const float4*)g_Mpart;
    float4 s = src[i];
    #pragma unroll
    for (int ks = 1; ks < KSPLIT; ks++) {
        float4 v = src[(size_t)ks * n4 + i];
        s.x += v.x;  s.y += v.y;  s.z += v.z;  s.w += v.w;
    }
    const float sc = 1.0f / DKd;
    __nv_bfloat162 two[2] = { __floats2bfloat162_rn(s.x * sc, s.y * sc),
                              __floats2bfloat162_rn(s.z * sc, s.w * sc) };
    *(uint2*)&g_M[(size_t)i * 4] = *(uint2*)two;
}

// ---------------- womt (R3-proven direct-global-load shape): ---------------
// Wp_b[c, h*64+d] = sum_e Wo[c, h*64+e] * M~_bh[d,e]
__global__ void womt_kernel() {
    const int c0 = blockIdx.x * 64, h = blockIdx.y, b = blockIdx.z;
    const bf16* Mbh = g_M + ((size_t)(b * NH + h)) * DKd * DKd;
    __shared__ __align__(16) float Cs[64][68];
    const int tid = threadIdx.x;
    const int warp = tid >> 5, wr = warp >> 1, wc = warp & 1;

    wmma::fragment<wmma::accumulator,16,16,16,float> acc[2][2];
    #pragma unroll
    for (int i = 0; i < 2; i++)
        #pragma unroll
        for (int j = 0; j < 2; j++) wmma::fill_fragment(acc[i][j], 0.0f);

    #pragma unroll
    for (int kt = 0; kt < 4; kt++) {
        wmma::fragment<wmma::matrix_a,16,16,16,bf16,wmma::row_major> af[2];
        wmma::fragment<wmma::matrix_b,16,16,16,bf16,wmma::col_major> bg[2];
        #pragma unroll
        for (int i = 0; i < 2; i++)
            wmma::load_matrix_sync(af[i],
                g_Wo + (size_t)(c0 + wr*32 + i*16) * ODd + h * DKd + kt*16, ODd);
        #pragma unroll
        for (int j = 0; j < 2; j++)
            wmma::load_matrix_sync(bg[j],
                Mbh + (size_t)(wc*32 + j*16) * DKd + kt*16, DKd);
        #pragma unroll
        for (int i = 0; i < 2; i++)
            #pragma unroll
            for (int j = 0; j < 2; j++)
                wmma::mma_sync(acc[i][j], af[i], bg[j], acc[i][j]);
    }
    #pragma unroll
    for (int i = 0; i < 2; i++)
        #pragma unroll
        for (int j = 0; j < 2; j++)
            wmma::store_matrix_sync(&Cs[wr*32 + i*16][wc*32 + j*16], acc[i][j], 68,
                                    wmma::mem_row_major);
    __syncthreads();

    bf16* outp = g_Wp + (size_t)b * CQd * ODd;
    #pragma unroll
    for (int t = tid; t < 1024; t += 128) {   // 64x64, 4-wide
        int r = t >> 4, c4 = (t & 15) * 4;
        float4 v = *(float4*)&Cs[r][c4];
        __nv_bfloat162 two[2] = { __floats2bfloat162_rn(v.x, v.y),
                                  __floats2bfloat162_rn(v.z, v.w) };
        *(uint2*)&outp[(size_t)(c0 + r) * ODd + h * DKd + c4] = *(uint2*)two;
    }
}

// ---------------------------------------------------------------------------
extern "C" void kernel_launch(void* const* d_in, const int* in_sizes, int n_in,
                              void* d_out, int out_size) {
    const float* xq    = (const float*)d_in[0];
    const float* xkv   = (const float*)d_in[1];
    const float* Wq    = (const float*)d_in[2];
    const float* Wk    = (const float*)d_in[3];
    const float* Wv    = (const float*)d_in[4];
    const float* Wo    = (const float*)d_in[5];
    const float* gamma = (const float*)d_in[6];
    float* out = (float*)d_out;

    cudaFuncSetAttribute(proj_kernel,  cudaFuncAttributeMaxDynamicSharedMemorySize, 69632);
    cudaFuncSetAttribute(final_kernel, cudaFuncAttributeMaxDynamicSharedMemorySize, 34816);

    // 1) convert everything to bf16 (one launch)
    convert_all_kernel<<<4608, 256>>>(xq, xkv, Wq, Wk, Wv, Wo);

    // 2) Q/K/V projections (one launch, z = b*3 + which)
    ProjArgs pa;
    void *p;
    cudaGetSymbolAddress(&p, g_Wq);  pa.W[0] = (const bf16*)p;
    cudaGetSymbolAddress(&p, g_Wk);  pa.W[1] = (const bf16*)p;
    cudaGetSymbolAddress(&p, g_Wv);  pa.W[2] = (const bf16*)p;
    cudaGetSymbolAddress(&p, g_xq);  pa.X[0] = (const bf16*)p;
    cudaGetSymbolAddress(&p, g_xkv); pa.X[1] = (const bf16*)p;
    cudaGetSymbolAddress(&p, g_Q);   pa.Y[0] = (bf16*)p;
    cudaGetSymbolAddress(&p, g_K);   pa.Y[1] = (bf16*)p;
    cudaGetSymbolAddress(&p, g_V);   pa.Y[2] = (bf16*)p;
    proj_kernel<<<dim3(NQd/128, ODd/128, BATCH*3), 256, 67584>>>(pa);

    // 3) M partials (256 CTAs) -> parallel reduce -> womt (direct loads)
    kv_outer_kernel<<<dim3(KSPLIT, NH, BATCH), 128>>>();
    reduce_m_kernel<<<128, 256>>>();
    womt_kernel<<<dim3(CQd/64, NH, BATCH), 128>>>();

    // 4) out = gamma * (Wp_b @ Q_b) + x_q
    final_kernel<<<dim3(NQd/128, CQd/64, BATCH), 256, 33792>>>(xq, gamma, out);
}